// round 9
// baseline (speedup 1.0000x reference)
#include <cuda_runtime.h>
#include <stdint.h>

// ---------------------------------------------------------------------------
// BoltzmannGateSTE: keep top-k (k = int(n/e)) by |x|, zero the rest.
// R9: replace the 2^20-bin window histogram (4MB zero + 8us supers_scan) with
// a 2^14-bin hist (64KB) + one refine pass over the compacted list.
//   K1 zero_small:  zero 82KB scratch + counters + barrier state
//   K2 fused_p1:    read x once -> speculative out, stage window elems to
//                   list + 2^14-bin hist; LAST block verifies (ticket).
//   K3 resolve_fix: scan h1 -> boundary bin (64 ulps); refine exact 64-bin
//                   hist from list; scan -> exact tbits; scatter fixup.
//                   (cold fallback: full 3-level radix select + re-mask)
// ---------------------------------------------------------------------------

#define NH1     16384          // 2^14 bins over the 2^20-ulp window (64 ulps/bin)
#define NCOARSE 4096
#define LISTCAP (1 << 22)      // 4M entries (expected ~1.11M)
#define CAPB    2048           // per-block staging (expected ~1081/block)
#define GRID    1024
#define BLK     256
#define STRIDE  (GRID * BLK)
#define WLO_N   0x3F600000u    // bits(0.875f)
#define WSPAN_N (1u << 20)     // window = exactly 2^20 ulp-groups
#define WHI_N   (WLO_N + WSPAN_N)   // bits(0.9375f)

__device__ __align__(16) unsigned g_h1[NH1];
__device__ unsigned g_h2[64];
__device__ unsigned g_coarse[NCOARSE];
__device__ unsigned g_A;
__device__ unsigned g_listcnt;
__device__ unsigned g_overflow;
__device__ unsigned g_mode;
__device__ unsigned g_krem;
__device__ unsigned g_sel;         // rank_desc outputs
__device__ unsigned g_rem2;
__device__ unsigned g_tbits;
__device__ unsigned g_done1;       // K2 verification ticket
__device__ unsigned g_bar_cnt;     // K3 grid barrier
__device__ volatile unsigned g_bar_sense;
__device__ uint2    g_list[LISTCAP];

// ---------------- K1: zero scratch + barrier state (runs each replay) ------
__global__ void zero_small() {
    int idx = blockIdx.x * blockDim.x + threadIdx.x;
    int stride = gridDim.x * blockDim.x;
    for (int i = idx; i < NH1; i += stride) g_h1[i] = 0;
    for (int i = idx; i < NCOARSE; i += stride) g_coarse[i] = 0;
    if (idx < 64) g_h2[idx] = 0;
    if (idx == 0) {
        g_A = 0; g_listcnt = 0; g_overflow = 0; g_mode = 0;
        g_done1 = 0; g_bar_cnt = 0; g_bar_sense = 0;
    }
}

// ---------------- K2: fused streaming pass + last-block verify -------------
__global__ void __launch_bounds__(BLK)
fused_p1(const float4* __restrict__ x, float4* __restrict__ out,
         int n4, int rem, unsigned k)
{
    __shared__ uint2 sbuf[CAPB];          // 16KB staging
    __shared__ unsigned scratch[BLK];     // 1KB reduce
    __shared__ unsigned svar[4];          // 0:scnt 1:sbase
    const int tid = threadIdx.x;
    const int gtid = blockIdx.x * BLK + tid;
    const float* xs = (const float*)x;
    float* outs = (float*)out;

    if (tid == 0) svar[0] = 0;
    __syncthreads();

    unsigned cntHi = 0;
#define DO1(f, eidx, odst) { \
    unsigned raw = __float_as_uint(f); \
    unsigned u = raw & 0x7FFFFFFFu; \
    odst = (u >= WHI_N) ? f : 0.0f; \
    cntHi += (u >= WHI_N); \
    if (u - WLO_N < WSPAN_N) { \
        unsigned p = atomicAdd(&svar[0], 1u); \
        if (p < CAPB) { sbuf[p].x = (eidx); sbuf[p].y = raw; } \
    } \
}
#define DO4(vv, fi) { \
    float4 o; \
    unsigned eb = (unsigned)(fi) * 4u; \
    DO1(vv.x, eb + 0u, o.x); \
    DO1(vv.y, eb + 1u, o.y); \
    DO1(vv.z, eb + 2u, o.z); \
    DO1(vv.w, eb + 3u, o.w); \
    __stcs(&out[fi], o); \
}
    {
        int i = gtid;
        for (; i + STRIDE < n4; i += 2 * STRIDE) {
            float4 v0 = __ldcs(&x[i]);
            float4 v1 = __ldcs(&x[i + STRIDE]);
            DO4(v0, i);
            DO4(v1, i + STRIDE);
        }
        for (; i < n4; i += STRIDE) {
            float4 v = __ldcs(&x[i]);
            DO4(v, i);
        }
    }
#undef DO4
#undef DO1
    if (gtid < rem) {   // scalar tail
        float f = xs[n4 * 4 + gtid];
        unsigned raw = __float_as_uint(f);
        unsigned u = raw & 0x7FFFFFFFu;
        cntHi += (u >= WHI_N);
        outs[n4 * 4 + gtid] = (u >= WHI_N) ? f : 0.0f;
        if (u - WLO_N < WSPAN_N) {
            unsigned p = atomicAdd(&svar[0], 1u);
            if (p < CAPB) { sbuf[p].x = (unsigned)(n4 * 4 + gtid); sbuf[p].y = raw; }
        }
    }

    // block-reduce cntHi; reserve list space
    scratch[tid] = cntHi;
    __syncthreads();
    for (int off = BLK / 2; off > 0; off >>= 1) {
        if (tid < off) scratch[tid] += scratch[tid + off];
        __syncthreads();
    }
    if (tid == 0) {
        if (scratch[0]) atomicAdd(&g_A, scratch[0]);
        unsigned c = svar[0];
        if (c > CAPB) { c = CAPB; g_overflow = 1u; }
        unsigned base = atomicAdd(&g_listcnt, c);
        if (base + c > LISTCAP) g_overflow = 1u;
        svar[0] = c;
        svar[1] = base;
    }
    __syncthreads();
    {   // flush staging -> list + 2^14-bin window histogram
        unsigned c = svar[0], base = svar[1];
        for (unsigned j = tid; j < c; j += BLK) {
            uint2 e = sbuf[j];
            if (base + j < LISTCAP) g_list[base + j] = e;
            atomicAdd(&g_h1[((e.y & 0x7FFFFFFFu) - WLO_N) >> 6], 1u);
        }
    }
    // last block out performs verification
    __syncthreads();
    __threadfence();
    if (tid == 0) {
        if (atomicAdd(&g_done1, 1u) == GRID - 1u) {
            __threadfence();
            unsigned A = g_A, cnt = g_listcnt, ov = g_overflow;
            unsigned mode = 1u;
            if (!ov && A < k && (k - A) <= cnt) {
                mode = 0u; g_krem = k - A;
            }
            g_mode = mode;
        }
    }
}

// ---------------- K3: resolve + fixup (one kernel, internal grid sync) -----
__device__ __forceinline__ void gbar(unsigned* sense_smem) {
    __syncthreads();
    if (threadIdx.x == 0) {
        unsigned s = *sense_smem ^ 1u;
        *sense_smem = s;
        __threadfence();
        if (atomicAdd(&g_bar_cnt, 1u) == GRID - 1u) {
            g_bar_cnt = 0u;
            __threadfence();
            g_bar_sense = s;
        } else {
            while (g_bar_sense != s) __nanosleep(64);
            __threadfence();
        }
    }
    __syncthreads();
}

// block-wide descending-rank search: find bin where cumulative-from-top
// first reaches krem. Writes bin -> g_sel, residual -> g_rem2.
__device__ void rank_desc(const unsigned* __restrict__ bins, int nbins,
                          unsigned krem, unsigned* scratch) {
    const int t = threadIdx.x;
    int per = nbins >> 8; if (per == 0) per = 1;
    int nth = nbins / per;
    unsigned sum = 0;
    if (t < nth)
        for (int j = 0; j < per; j++) sum += bins[t * per + j];
    scratch[t] = sum;
    __syncthreads();
    for (int off = 1; off < BLK; off <<= 1) {
        unsigned add = (t + off < BLK) ? scratch[t + off] : 0u;
        __syncthreads();
        scratch[t] += add;
        __syncthreads();
    }
    unsigned above = (t < BLK - 1) ? scratch[t + 1] : 0u;
    if (t < nth && above < krem && above + sum >= krem) {
        unsigned cum = above;
        for (int j = per - 1; j >= 0; j--) {
            unsigned c = bins[t * per + j];
            unsigned prev = cum;
            cum += c;
            if (cum >= krem && prev < krem) { g_sel = (unsigned)(t * per + j); g_rem2 = krem - prev; }
        }
    }
    __syncthreads();
}

__global__ void __launch_bounds__(BLK)
resolve_fix(const float4* __restrict__ x, float4* __restrict__ out,
            int n4, int rem, unsigned k)
{
    __shared__ unsigned scratch[BLK];
    __shared__ unsigned svar[4];   // 2: barrier sense
    const int tid = threadIdx.x;
    const int gtid = blockIdx.x * BLK + tid;
    const float* xs = (const float*)x;
    float* outs = (float*)out;
    if (tid < 4) svar[tid] = 0;
    __syncthreads();

    const unsigned mode = g_mode;
    unsigned cnt = g_listcnt;
    if (cnt > LISTCAP) cnt = LISTCAP;

    if (mode == 0u) {
        // ---- scan h1 -> boundary 64-ulp bin
        if (blockIdx.x == 0) rank_desc(g_h1, NH1, g_krem, scratch);
        gbar(&svar[2]);
        const unsigned b1base = WLO_N + (g_sel << 6);
        const unsigned rem2 = g_rem2;
        // ---- refine: exact 64-bin hist of list entries in the boundary bin
        for (unsigned j = (unsigned)gtid; j < cnt; j += STRIDE) {
            unsigned u = g_list[j].y & 0x7FFFFFFFu;
            unsigned d = u - b1base;
            if (d < 64u) atomicAdd(&g_h2[d], 1u);
        }
        gbar(&svar[2]);
        if (blockIdx.x == 0) {
            rank_desc(g_h2, 64, rem2, scratch);
            if (tid == 0) g_tbits = b1base + g_sel;
        }
        gbar(&svar[2]);
        // ---- fixup: scatter keepers from list (list is L2-hot)
        const unsigned tb = g_tbits;
        for (unsigned j = (unsigned)gtid; j < cnt; j += STRIDE) {
            uint2 e = g_list[j];
            if ((e.y & 0x7FFFFFFFu) >= tb) outs[e.x] = __uint_as_float(e.y);
        }
    } else {
        // =========== COLD fallback: exact 3-level radix select =============
        const int TOT = STRIDE;
        // zero partially-filled scratch hists
        for (int i = gtid; i < NH1; i += TOT) g_h1[i] = 0;
        if (gtid < 64) g_h2[gtid] = 0;
        gbar(&svar[2]);
        // level 1: coarse 4096 (2^19-wide)
        for (int i = gtid; i < n4; i += TOT) {
            float4 v = x[i];
            atomicAdd(&g_coarse[(__float_as_uint(v.x) & 0x7FFFFFFFu) >> 19], 1u);
            atomicAdd(&g_coarse[(__float_as_uint(v.y) & 0x7FFFFFFFu) >> 19], 1u);
            atomicAdd(&g_coarse[(__float_as_uint(v.z) & 0x7FFFFFFFu) >> 19], 1u);
            atomicAdd(&g_coarse[(__float_as_uint(v.w) & 0x7FFFFFFFu) >> 19], 1u);
        }
        for (int g = gtid; g < rem; g += TOT)
            atomicAdd(&g_coarse[(__float_as_uint(xs[n4 * 4 + g]) & 0x7FFFFFFFu) >> 19], 1u);
        gbar(&svar[2]);
        if (blockIdx.x == 0) rank_desc(g_coarse, NCOARSE, k, scratch);
        gbar(&svar[2]);
        const unsigned base0 = g_sel << 19;
        const unsigned krem1 = g_rem2;
        // level 2: 2^14 bins of width 32 over [base0, base0 + 2^19)
        for (int i = gtid; i < n4; i += TOT) {
            float4 v = x[i];
            unsigned u0 = __float_as_uint(v.x) & 0x7FFFFFFFu;
            unsigned u1 = __float_as_uint(v.y) & 0x7FFFFFFFu;
            unsigned u2 = __float_as_uint(v.z) & 0x7FFFFFFFu;
            unsigned u3 = __float_as_uint(v.w) & 0x7FFFFFFFu;
            if (u0 - base0 < (1u << 19)) atomicAdd(&g_h1[(u0 - base0) >> 5], 1u);
            if (u1 - base0 < (1u << 19)) atomicAdd(&g_h1[(u1 - base0) >> 5], 1u);
            if (u2 - base0 < (1u << 19)) atomicAdd(&g_h1[(u2 - base0) >> 5], 1u);
            if (u3 - base0 < (1u << 19)) atomicAdd(&g_h1[(u3 - base0) >> 5], 1u);
        }
        for (int g = gtid; g < rem; g += TOT) {
            unsigned u = __float_as_uint(xs[n4 * 4 + g]) & 0x7FFFFFFFu;
            if (u - base0 < (1u << 19)) atomicAdd(&g_h1[(u - base0) >> 5], 1u);
        }
        gbar(&svar[2]);
        if (blockIdx.x == 0) rank_desc(g_h1, NH1, krem1, scratch);
        gbar(&svar[2]);
        const unsigned base1 = base0 + (g_sel << 5);
        const unsigned krem2 = g_rem2;
        // level 3: 32 bins of width 1
        for (int i = gtid; i < n4; i += TOT) {
            float4 v = x[i];
            unsigned u0 = __float_as_uint(v.x) & 0x7FFFFFFFu;
            unsigned u1 = __float_as_uint(v.y) & 0x7FFFFFFFu;
            unsigned u2 = __float_as_uint(v.z) & 0x7FFFFFFFu;
            unsigned u3 = __float_as_uint(v.w) & 0x7FFFFFFFu;
            if (u0 - base1 < 32u) atomicAdd(&g_h2[u0 - base1], 1u);
            if (u1 - base1 < 32u) atomicAdd(&g_h2[u1 - base1], 1u);
            if (u2 - base1 < 32u) atomicAdd(&g_h2[u2 - base1], 1u);
            if (u3 - base1 < 32u) atomicAdd(&g_h2[u3 - base1], 1u);
        }
        for (int g = gtid; g < rem; g += TOT) {
            unsigned u = __float_as_uint(xs[n4 * 4 + g]) & 0x7FFFFFFFu;
            if (u - base1 < 32u) atomicAdd(&g_h2[u - base1], 1u);
        }
        gbar(&svar[2]);
        if (blockIdx.x == 0) {
            rank_desc(g_h2, 32, krem2, scratch);
            if (tid == 0) g_tbits = base1 + g_sel;
        }
        gbar(&svar[2]);
        // full exact re-mask
        const unsigned tb = g_tbits;
        for (int i = gtid; i < n4; i += TOT) {
            float4 v = x[i];
            v.x = ((__float_as_uint(v.x) & 0x7FFFFFFFu) >= tb) ? v.x : 0.0f;
            v.y = ((__float_as_uint(v.y) & 0x7FFFFFFFu) >= tb) ? v.y : 0.0f;
            v.z = ((__float_as_uint(v.z) & 0x7FFFFFFFu) >= tb) ? v.z : 0.0f;
            v.w = ((__float_as_uint(v.w) & 0x7FFFFFFFu) >= tb) ? v.w : 0.0f;
            out[i] = v;
        }
        for (int g = gtid; g < rem; g += TOT) {
            float f = xs[n4 * 4 + g];
            outs[n4 * 4 + g] = ((__float_as_uint(f) & 0x7FFFFFFFu) >= tb) ? f : 0.0f;
        }
    }
}

__global__ void copy_all(const float4* __restrict__ x, float4* __restrict__ out, int n4) {
    int idx = blockIdx.x * blockDim.x + threadIdx.x;
    int stride = gridDim.x * blockDim.x;
    for (int i = idx; i < n4; i += stride) out[i] = x[i];
}

extern "C" void kernel_launch(void* const* d_in, const int* in_sizes, int n_in,
                              void* d_out, int out_size) {
    const float* x = (const float*)d_in[0];
    float* out = (float*)d_out;
    int n = in_sizes[0];

    // k = max(1, int(n * (1.0/e))) — bit-exact replication of the Python.
    const double FRACTION = 1.0 / 2.718281828459045235360287;
    long long kll = (long long)((double)n * FRACTION);
    if (kll < 1) kll = 1;

    int n4 = n >> 2;
    int rem = n & 3;

    if (kll >= (long long)n) {
        copy_all<<<GRID, BLK>>>((const float4*)x, (float4*)out, n4);
        return;
    }
    unsigned k = (unsigned)kll;

    zero_small<<<64, BLK>>>();
    fused_p1<<<GRID, BLK>>>((const float4*)x, (float4*)out, n4, rem, k);
    resolve_fix<<<GRID, BLK>>>((const float4*)x, (float4*)out, n4, rem, k);
}